// round 15
// baseline (speedup 1.0000x reference)
#include <cuda_runtime.h>
#include <cuda_fp16.h>
#include <math.h>
#include <stdint.h>

#define Bk 8
#define Nn 8192
#define Ee 16384
#define Dd 128
#define Mm 20
#define Ll 3
#define Rr 200

// ---- edge kernel geometry (M-split: 64 edges x 128 out per CTA) ----
#define CH 32
#define ESTR 40
#define EAT (64*ESTR)             // A tile halves (64 rows)
#define EBT (128*ESTR)            // B tile halves (128 n-rows)
#define EB_BASE (2*EAT)           // B offset within stage (halves)
#define ESTAGE (2*EAT + 2*EBT)    // 15360 halves = 30720 B
#define ESMEM (2*ESTAGE*2)        // 61440 B, 2 stages
#define NCH 12

// ---- update kernel geometry (validated R14: N-split) ----
#define USTR 72
#define UAT (128*USTR)
#define UBT (64*USTR)
#define UB_BASE (2*UAT)
#define USMEM ((2*UAT + 4*UBT)*2)

// -------- device scratch --------
__device__ float g_h[(size_t)Bk*Nn*Dd];
__device__ float g_aggr[Ll][(size_t)Bk*Nn*Dd];
__device__ float g_scores[Bk*Nn];
__device__ float g_tblD[Ll*10*Dd];
__device__ float g_tblR[Ll*Rr*Dd];
__device__ __half g_hhi[(size_t)Bk*Nn*Dd],  g_hlo[(size_t)Bk*Nn*Dd];
__device__ __half g_confhi[(size_t)Bk*Ee*Dd], g_conflo[(size_t)Bk*Ee*Dd];
__device__ __half g_msgWhi[(size_t)Ll*20*128*32], g_msgWlo[(size_t)Ll*20*128*32];
__device__ __half g_updWhi[(size_t)Ll*2*128*64],  g_updWlo[(size_t)Ll*2*128*64];

__device__ __forceinline__ uint32_t smem_u32(const void* p){
    uint32_t a;
    asm("{ .reg .u64 t; cvta.to.shared.u64 t, %1; cvt.u32.u64 %0, t; }" : "=r"(a) : "l"(p));
    return a;
}
__device__ __forceinline__ void cpa16(uint32_t dst, const void* src){
    asm volatile("cp.async.cg.shared.global [%0], [%1], 16;" :: "r"(dst), "l"(src));
}
#define CP_COMMIT() asm volatile("cp.async.commit_group;" ::: "memory")

#define LDSM4(r, addr) \
    asm volatile("ldmatrix.sync.aligned.m8n8.x4.shared.b16 {%0,%1,%2,%3}, [%4];" \
        : "=r"((r)[0]), "=r"((r)[1]), "=r"((r)[2]), "=r"((r)[3]) : "r"(addr))

#define MMA_F16(c, a, b0, b1) \
    asm volatile("mma.sync.aligned.m16n8k16.row.col.f32.f16.f16.f32 " \
        "{%0,%1,%2,%3}, {%4,%5,%6,%7}, {%8,%9}, {%0,%1,%2,%3};" \
        : "+f"((c)[0]), "+f"((c)[1]), "+f"((c)[2]), "+f"((c)[3]) \
        : "r"((a)[0]), "r"((a)[1]), "r"((a)[2]), "r"((a)[3]), "r"(b0), "r"(b1))

__device__ __forceinline__ void pack2(float2 v, uint32_t& hi, uint32_t& lo){
    __half h0 = __float2half_rn(v.x), h1 = __float2half_rn(v.y);
    __half2 H = __halves2half2(h0, h1);
    __half2 L = __halves2half2(__float2half_rn(v.x - __half2float(h0)),
                               __float2half_rn(v.y - __half2float(h1)));
    hi = *(uint32_t*)&H; lo = *(uint32_t*)&L;
}

// ---------------- prep: h init + fp16 splits + zero all aggr buffers ----------------
__global__ void prep_kernel(const int* __restrict__ dists,
                            const float* __restrict__ noise,
                            const float* __restrict__ dtab)
{
    int i = blockIdx.x * blockDim.x + threadIdx.x;
    if (i >= Bk*Nn*Dd/4) return;
    int node = i >> 5;
    int c = i & 31;
    int di = dists[node];
    di = di < 0 ? 0 : (di > 9 ? 9 : di);
    float4 dv = __ldg(((const float4*)(dtab + (size_t)di*Dd)) + c);
    float4 nz = ((const float4*)noise)[i];
    float4 h;
    h.x = dv.x + 0.1f*nz.x; h.y = dv.y + 0.1f*nz.y;
    h.z = dv.z + 0.1f*nz.z; h.w = dv.w + 0.1f*nz.w;
    ((float4*)g_h)[i]  = h;
    float4 z = make_float4(0.f, 0.f, 0.f, 0.f);
    ((float4*)g_aggr[0])[i] = z;
    ((float4*)g_aggr[1])[i] = z;
    ((float4*)g_aggr[2])[i] = z;

    uint32_t hiA, loA, hiB, loB;
    pack2(make_float2(h.x, h.y), hiA, loA);
    pack2(make_float2(h.z, h.w), hiB, loB);
    ((uint32_t*)g_hhi)[2*i] = hiA; ((uint32_t*)g_hhi)[2*i+1] = hiB;
    ((uint32_t*)g_hlo)[2*i] = loA; ((uint32_t*)g_hlo)[2*i+1] = loB;
}

// ---------------- fused prep: conf split + weight split + tables ----------------
#define AUXN (Bk*Ee*Dd/4)
#define MSGTOT (Ll*5*Dd*Dd)
#define WTSN (MSGTOT + Ll*Dd*Dd)
#define TBLN (Ll*(10+Rr)*Dd)

__global__ void prep_misc(const float* __restrict__ conf,
                          const float* __restrict__ dtab,
                          const float* __restrict__ rel_table,
                          const float* __restrict__ msgW,
                          const float* __restrict__ updW)
{
    int i = blockIdx.x * blockDim.x + threadIdx.x;
    if (i < AUXN) {
        float4 v = ((const float4*)conf)[i];
        int base = i*4;
        uint32_t hiA, loA, hiB, loB;
        pack2(make_float2(v.x, v.y), hiA, loA);
        pack2(make_float2(v.z, v.w), hiB, loB);
        *(uint32_t*)(g_confhi + base)     = hiA;
        *(uint32_t*)(g_confhi + base + 2) = hiB;
        *(uint32_t*)(g_conflo + base)     = loA;
        *(uint32_t*)(g_conflo + base + 2) = loB;
        return;
    }
    int j = i - AUXN;
    if (j < WTSN) {
        if (j < MSGTOT) {
            int l = j / (640*128);
            int k = (j / 128) % 640;
            int n = j & 127;
            int ch = k >> 5, kk = k & 31;
            float w = msgW[j];
            __half hi = __float2half_rn(w);
            __half lo = __float2half_rn(w - __half2float(hi));
            size_t o = (((size_t)(l*20 + ch))*128 + n)*32 + kk;
            g_msgWhi[o] = hi; g_msgWlo[o] = lo;
        } else {
            int q = j - MSGTOT;
            int l = q / (128*128);
            int k = (q / 128) % 128;
            int n = q & 127;
            int ch = k >> 6, kk = k & 63;
            float w = updW[q];
            __half hi = __float2half_rn(w);
            __half lo = __float2half_rn(w - __half2float(hi));
            size_t o = (((size_t)(l*2 + ch))*128 + n)*64 + kk;
            g_updWhi[o] = hi; g_updWlo[o] = lo;
        }
        return;
    }
    int t = j - WTSN;
    if (t >= TBLN) return;
    {
        int n = t & 127;
        int row = (t >> 7) % (10+Rr);
        int l = t / ((10+Rr)*Dd);
        const float* Wl = msgW + (size_t)l*640*128;
        const float* vec; const float* w; float* dst;
        if (row < 10) {
            vec = dtab + row*Dd;
            w = Wl + (size_t)2*128*128;
            dst = g_tblD + (l*10 + row)*Dd + n;
        } else {
            vec = rel_table + (size_t)(row-10)*Dd;
            w = Wl + (size_t)3*128*128;
            dst = g_tblR + ((size_t)l*Rr + (row-10))*Dd + n;
        }
        float s0=0.f, s1=0.f, s2=0.f, s3=0.f;
        #pragma unroll
        for (int k = 0; k < 128; k += 4) {
            s0 = fmaf(vec[k],   __ldg(w + (size_t)k*128 + n),     s0);
            s1 = fmaf(vec[k+1], __ldg(w + (size_t)(k+1)*128 + n), s1);
            s2 = fmaf(vec[k+2], __ldg(w + (size_t)(k+2)*128 + n), s2);
            s3 = fmaf(vec[k+3], __ldg(w + (size_t)(k+3)*128 + n), s3);
        }
        *dst = (s0 + s1) + (s2 + s3);
    }
}

// ---------------- edge GEMM v2: M-split, 64 edges x 128 out, 3 CTA/SM ----------------
// stage halves: [0] A_hi(64xESTR), [EAT] A_lo, [EB_BASE] B_hi(128xESTR), [+EBT] B_lo
__global__ void __launch_bounds__(256, 3)
edge_hmma_kernel(int layer,
                 const int* __restrict__ edge_index,
                 const int* __restrict__ rels,
                 const int* __restrict__ edge_mask,
                 const int* __restrict__ dists,
                 const float* __restrict__ rel_table,
                 const float* __restrict__ bias)
{
    extern __shared__ __half sm[];
    __shared__ int   s_src[64], s_tgt[64], s_rel[64], s_di[64];
    __shared__ float s_em[64], s_bias[128];

    int tid = threadIdx.x, wid = tid >> 5, lane = tid & 31;
    int b  = blockIdx.x >> 8;               // Ee/64 = 256 tiles
    int e0 = (blockIdx.x & 255) << 6;
    size_t bN = (size_t)b * Nn;

    if (tid < 64) {
        int e = e0 + tid;
        int src = edge_index[(size_t)b*2*Ee + e];
        s_src[tid] = src;
        s_tgt[tid] = edge_index[(size_t)b*2*Ee + Ee + e];
        s_rel[tid] = rels[(size_t)b*Ee + e];
        s_em[tid]  = edge_mask[(size_t)b*Ee + e] ? 1.f : 0.f;
        int di = dists[bN + src];
        s_di[tid] = di < 0 ? 0 : (di > 9 ? 9 : di);
    }
    if (tid < 128) s_bias[tid] = bias[tid];
    __syncthreads();

    uint32_t smb = smem_u32(sm);
    int wm = wid & 1, wn = wid >> 1;        // 2(M) x 4(N), warp tile 32x32
    int g = lane >> 2, t4 = lane & 3;

    float acc[2][4][4];
    #pragma unroll
    for (int i = 0; i < 2; i++)
        #pragma unroll
        for (int j = 0; j < 4; j++)
            #pragma unroll
            for (int q = 0; q < 4; q++) acc[i][j][q] = 0.f;

    auto issue = [&](int c, int st){
        uint32_t sb = smb + (uint32_t)(st*ESTAGE)*2;
        int wc = (c < 4) ? (4 + c) : ((c < 8) ? (12 + c) : (c - 8));
        const __half* wh = g_msgWhi + ((size_t)(layer*20 + wc))*4096;
        const __half* wl = g_msgWlo + ((size_t)(layer*20 + wc))*4096;
        #pragma unroll
        for (int r = 0; r < 2; r++){
            int idx = tid + r*256;
            int n = idx >> 2, f = idx & 3;
            uint32_t d = sb + (uint32_t)(EB_BASE + n*ESTR + f*8)*2;
            cpa16(d,           wh + n*32 + f*8);
            cpa16(d + EBT*2,   wl + n*32 + f*8);
        }
        if (c < 8){
            int koff = (c & 3)*CH;
            int e = tid >> 2, q = tid & 3;   // 64 edges x 4 quarters = 256
            size_t rowoff;
            const __half *ph, *pl;
            if (c < 4) { rowoff = (bN + s_src[e])*Dd; ph = g_hhi; pl = g_hlo; }
            else       { rowoff = ((size_t)b*Ee + e0 + e)*Dd; ph = g_confhi; pl = g_conflo; }
            uint32_t d = sb + (uint32_t)(e*ESTR + q*8)*2;
            cpa16(d,           ph + rowoff + koff + q*8);
            cpa16(d + EAT*2,   pl + rowoff + koff + q*8);
        }
    };
    auto fill0 = [&](int c, int st){
        __half* base = sm + st*ESTAGE;
        int koff = (c - 8)*CH;
        int e = tid >> 2, q = tid & 3;
        const float* hp = g_h + (bN + s_src[e])*Dd + koff + q*8;
        const float* rp = rel_table + (size_t)s_rel[e]*Dd + koff + q*8;
        float4 h1 = *(const float4*)hp, h2 = *(const float4*)(hp + 4);
        float4 r1 = *(const float4*)rp, r2 = *(const float4*)(rp + 4);
        float pr[8] = {h1.x*r1.x, h1.y*r1.y, h1.z*r1.z, h1.w*r1.w,
                       h2.x*r2.x, h2.y*r2.y, h2.z*r2.z, h2.w*r2.w};
        __half hh[8], ll[8];
        #pragma unroll
        for (int u = 0; u < 8; u++){
            hh[u] = __float2half_rn(pr[u]);
            ll[u] = __float2half_rn(pr[u] - __half2float(hh[u]));
        }
        *(uint4*)(base + e*ESTR + q*8)        = *(uint4*)hh;
        *(uint4*)(base + EAT + e*ESTR + q*8)  = *(uint4*)ll;
    };

    issue(0, 0); CP_COMMIT();

    for (int c = 0; c < NCH; c++){
        int st = c & 1, nst = st ^ 1;
        if (c + 1 < NCH){
            issue(c + 1, nst);
            if (c + 1 >= 8) fill0(c + 1, nst);
            CP_COMMIT();
            asm volatile("cp.async.wait_group 1;" ::: "memory");
        } else {
            asm volatile("cp.async.wait_group 0;" ::: "memory");
        }
        __syncthreads();

        uint32_t sb = smb + (uint32_t)(st*ESTAGE)*2;
        #pragma unroll
        for (int k16 = 0; k16 < 2; k16++){
            int kb = k16*16;
            uint32_t ah[2][4], al[2][4];
            #pragma unroll
            for (int i = 0; i < 2; i++){
                uint32_t a = sb + (uint32_t)((wm*32 + i*16 + (lane & 15))*ESTR + kb + (lane >> 4)*8)*2;
                LDSM4(ah[i], a);
                LDSM4(al[i], a + EAT*2);
            }
            uint32_t bh[2][4], bl[2][4];
            {
                uint32_t bb = sb + (uint32_t)(EB_BASE + (wn*32 + (lane & 15))*ESTR + kb + (lane >> 4)*8)*2;
                LDSM4(bh[0], bb);
                LDSM4(bl[0], bb + EBT*2);
            }
            #pragma unroll
            for (int jp = 0; jp < 2; jp++){
                int cur = jp & 1, nxt = cur ^ 1;
                if (jp < 1){
                    uint32_t bb = sb + (uint32_t)(EB_BASE + (wn*32 + 16 + (lane & 15))*ESTR + kb + (lane >> 4)*8)*2;
                    LDSM4(bh[nxt], bb);
                    LDSM4(bl[nxt], bb + EBT*2);
                }
                MMA_F16(acc[0][jp*2+0], ah[0], bh[cur][0], bh[cur][2]);
                MMA_F16(acc[0][jp*2+1], ah[0], bh[cur][1], bh[cur][3]);
                MMA_F16(acc[1][jp*2+0], ah[1], bh[cur][0], bh[cur][2]);
                MMA_F16(acc[1][jp*2+1], ah[1], bh[cur][1], bh[cur][3]);
                MMA_F16(acc[0][jp*2+0], ah[0], bl[cur][0], bl[cur][2]);
                MMA_F16(acc[0][jp*2+1], ah[0], bl[cur][1], bl[cur][3]);
                MMA_F16(acc[1][jp*2+0], ah[1], bl[cur][0], bl[cur][2]);
                MMA_F16(acc[1][jp*2+1], ah[1], bl[cur][1], bl[cur][3]);
                MMA_F16(acc[0][jp*2+0], al[0], bh[cur][0], bh[cur][2]);
                MMA_F16(acc[0][jp*2+1], al[0], bh[cur][1], bh[cur][3]);
                MMA_F16(acc[1][jp*2+0], al[1], bh[cur][0], bh[cur][2]);
                MMA_F16(acc[1][jp*2+1], al[1], bh[cur][1], bh[cur][3]);
            }
        }
        __syncthreads();
    }

    // epilogue: acc + bias + tblD + tblR -> relu -> masked scatter-add
    float* aggr = g_aggr[layer];
    #pragma unroll
    for (int i = 0; i < 2; i++) {
        #pragma unroll
        for (int half = 0; half < 2; half++) {
            int row = wm*32 + i*16 + g + half*8;
            if (s_em[row] != 0.f) {
                const float* tD = g_tblD + (layer*10 + s_di[row])*Dd;
                const float* tR = g_tblR + ((size_t)layer*Rr + s_rel[row])*Dd;
                float* dst = aggr + (bN + s_tgt[row])*Dd;
                #pragma unroll
                for (int j = 0; j < 4; j++) {
                    int col = wn*32 + j*8 + t4*2;
                    float add0 = s_bias[col]   + __ldg(tD + col)     + __ldg(tR + col);
                    float add1 = s_bias[col+1] + __ldg(tD + col + 1) + __ldg(tR + col + 1);
                    float v0 = acc[i][j][half*2+0] + add0;
                    float v1 = acc[i][j][half*2+1] + add1;
                    if (v0 > 0.f) atomicAdd(dst + col,     v0);
                    if (v1 > 0.f) atomicAdd(dst + col + 1, v1);
                }
            }
        }
    }
}

// ---------------- node update GEMM (validated R14: N-split, 3 CTA/SM) ----------------
__global__ void __launch_bounds__(256, 3)
update_hmma_kernel(int layer, int write_split, const float* __restrict__ bias)
{
    extern __shared__ __half sm[];
    __shared__ float s_bias[128];

    int tid = threadIdx.x, wid = tid >> 5, lane = tid & 31;
    size_t r0 = (size_t)(blockIdx.x >> 1) * 128;
    int nb = blockIdx.x & 1;
    uint32_t smb = smem_u32(sm);

    {
        const __half* wh = g_updWhi + (size_t)layer*2*8192 + nb*64*64;
        const __half* wl = g_updWlo + (size_t)layer*2*8192 + nb*64*64;
        #pragma unroll
        for (int it = 0; it < 4; it++) {
            int idx = tid + it*256;
            int c = idx >> 9, r = idx & 511;
            int n = r >> 3, q = r & 7;
            uint32_t dhi = smb + (uint32_t)(UB_BASE + 2*c*UBT + n*USTR + q*8)*2;
            cpa16(dhi,           wh + (size_t)c*8192 + n*64 + q*8);
            cpa16(dhi + UBT*2,   wl + (size_t)c*8192 + n*64 + q*8);
        }
        CP_COMMIT();
    }
    if (tid < 128) s_bias[tid] = bias[tid];

    int wm = wid & 3, wn = wid >> 2;
    int g = lane >> 2, t4 = lane & 3;
    const float* aggr = g_aggr[layer];

    float acc[2][4][4];
    #pragma unroll
    for (int i = 0; i < 2; i++)
        #pragma unroll
        for (int j = 0; j < 4; j++)
            #pragma unroll
            for (int q = 0; q < 4; q++) acc[i][j][q] = 0.f;

    for (int c = 0; c < 2; c++) {
        int koff = c*64;
        #pragma unroll
        for (int it = 0; it < 8; it++) {
            int idx = tid + it*256;
            int row = idx >> 4, q = idx & 15;
            float4 v = *(const float4*)(aggr + (r0 + row)*Dd + koff + q*4);
            __half h0 = __float2half_rn(v.x), h1 = __float2half_rn(v.y);
            __half h2 = __float2half_rn(v.z), h3 = __float2half_rn(v.w);
            int ho = row*USTR + q*4;
            *(__half2*)(sm + ho)           = __halves2half2(h0, h1);
            *(__half2*)(sm + ho + 2)       = __halves2half2(h2, h3);
            *(__half2*)(sm + UAT + ho)     = __halves2half2(__float2half_rn(v.x-__half2float(h0)), __float2half_rn(v.y-__half2float(h1)));
            *(__half2*)(sm + UAT + ho + 2) = __halves2half2(__float2half_rn(v.z-__half2float(h2)), __float2half_rn(v.w-__half2float(h3)));
        }
        if (c == 0) asm volatile("cp.async.wait_group 0;" ::: "memory");
        __syncthreads();

        uint32_t bbase = smb + (uint32_t)(UB_BASE + 2*c*UBT)*2;
        #pragma unroll
        for (int k16 = 0; k16 < 4; k16++) {
            int kb = k16*16;
            uint32_t ahi[2][4], alo[2][4];
            #pragma unroll
            for (int i = 0; i < 2; i++) {
                uint32_t a = smb + (uint32_t)((wm*32 + i*16 + (lane & 15))*USTR + kb + (lane >> 4)*8)*2;
                LDSM4(ahi[i], a);
                LDSM4(alo[i], a + UAT*2);
            }
            #pragma unroll
            for (int jp = 0; jp < 2; jp++) {
                uint32_t bb = bbase + (uint32_t)((wn*32 + jp*16 + (lane & 15))*USTR + kb + (lane >> 4)*8)*2;
                uint32_t bh[4], bl[4];
                LDSM4(bh, bb);
                LDSM4(bl, bb + UBT*2);
                MMA_F16(acc[0][jp*2+0], ahi[0], bh[0], bh[2]);
                MMA_F16(acc[0][jp*2+1], ahi[0], bh[1], bh[3]);
                MMA_F16(acc[1][jp*2+0], ahi[1], bh[0], bh[2]);
                MMA_F16(acc[1][jp*2+1], ahi[1], bh[1], bh[3]);
                MMA_F16(acc[0][jp*2+0], ahi[0], bl[0], bl[2]);
                MMA_F16(acc[0][jp*2+1], ahi[0], bl[1], bl[3]);
                MMA_F16(acc[1][jp*2+0], ahi[1], bl[0], bl[2]);
                MMA_F16(acc[1][jp*2+1], ahi[1], bl[1], bl[3]);
                MMA_F16(acc[0][jp*2+0], alo[0], bh[0], bh[2]);
                MMA_F16(acc[0][jp*2+1], alo[0], bh[1], bh[3]);
                MMA_F16(acc[1][jp*2+0], alo[1], bh[0], bh[2]);
                MMA_F16(acc[1][jp*2+1], alo[1], bh[1], bh[3]);
            }
        }
        __syncthreads();
    }

    #pragma unroll
    for (int i = 0; i < 2; i++) {
        #pragma unroll
        for (int half = 0; half < 2; half++) {
            int row = wm*32 + i*16 + g + half*8;
            size_t gro = (r0 + row)*Dd;
            float* hp = g_h + gro;
            #pragma unroll
            for (int j = 0; j < 4; j++) {
                int col = nb*64 + wn*32 + j*8 + t4*2;
                float2 hv = *(float2*)(hp + col);
                float v0 = hv.x + acc[i][j][half*2+0] + s_bias[col];
                float v1 = hv.y + acc[i][j][half*2+1] + s_bias[col+1];
                *(float2*)(hp + col) = make_float2(v0, v1);
                if (write_split) {
                    uint32_t hi, lo;
                    pack2(make_float2(v0, v1), hi, lo);
                    *(uint32_t*)(g_hhi + gro + col) = hi;
                    *(uint32_t*)(g_hlo + gro + col) = lo;
                }
            }
        }
    }
}

// ---------------- attention scores ----------------
__global__ void score_kernel(const float* __restrict__ attW, const float* __restrict__ attb,
                             const int* __restrict__ node_mask,
                             const float* __restrict__ rq)
{
    int gw = blockIdx.x*8 + (threadIdx.x >> 5);
    int lane = threadIdx.x & 31;
    int b = gw / Nn, n = gw % Nn;
    const float* hrow = g_h + (size_t)gw*Dd;
    float s = 0.f;
    #pragma unroll
    for (int i = 0; i < 4; i++) {
        int d = lane + i*32;
        s = fmaf(hrow[d], attW[d], s);
        s = fmaf(rq[b*Dd + d], attW[Dd + d], s);
    }
    #pragma unroll
    for (int o = 16; o; o >>= 1) s += __shfl_xor_sync(0xffffffffu, s, o);
    if (lane == 0) {
        s += attb[0];
        s = (s > 0.f) ? s : 0.01f * s;
        if (!node_mask[(size_t)b*Nn + n]) s = -1e9f;
        g_scores[gw] = s;
    }
}

// ---------------- softmax + top-20 + output (validated R10) ----------------
__global__ void __launch_bounds__(1024)
topk_kernel(const int* __restrict__ node_mask, float* __restrict__ out)
{
    __shared__ float ss[Nn];
    __shared__ float rv[32];
    __shared__ int   ri[32];
    __shared__ float s_red;
    __shared__ int   top_i[Mm];
    __shared__ float top_v[Mm];

    int b = blockIdx.x;
    int t = threadIdx.x;
    int w = t >> 5, lane = t & 31;

    for (int i = t; i < Nn; i += 1024) ss[i] = g_scores[(size_t)b*Nn + i];
    __syncthreads();

    float m = -INFINITY;
    for (int i = t; i < Nn; i += 1024) m = fmaxf(m, ss[i]);
    #pragma unroll
    for (int o = 16; o; o >>= 1) m = fmaxf(m, __shfl_xor_sync(0xffffffffu, m, o));
    if (lane == 0) rv[w] = m;
    __syncthreads();
    if (w == 0) {
        float v = rv[lane];
        #pragma unroll
        for (int o = 16; o; o >>= 1) v = fmaxf(v, __shfl_xor_sync(0xffffffffu, v, o));
        if (lane == 0) s_red = v;
    }
    __syncthreads();
    float vmax = s_red;

    float sum = 0.f;
    for (int i = t; i < Nn; i += 1024) sum += expf(ss[i] - vmax);
    #pragma unroll
    for (int o = 16; o; o >>= 1) sum += __shfl_xor_sync(0xffffffffu, sum, o);
    if (lane == 0) rv[w] = sum;
    __syncthreads();
    if (w == 0) {
        float v = rv[lane];
        #pragma unroll
        for (int o = 16; o; o >>= 1) v += __shfl_xor_sync(0xffffffffu, v, o);
        if (lane == 0) s_red = v;
    }
    __syncthreads();
    float inv = 1.f / s_red;

    for (int sel = 0; sel < Mm; sel++) {
        float bv = -INFINITY; int bi = Nn;
        for (int i = t; i < Nn; i += 1024) {
            float v = ss[i];
            if (v > bv) { bv = v; bi = i; }
        }
        #pragma unroll
        for (int o = 16; o; o >>= 1) {
            float ov = __shfl_xor_sync(0xffffffffu, bv, o);
            int   oi = __shfl_xor_sync(0xffffffffu, bi, o);
            if (ov > bv || (ov == bv && oi < bi)) { bv = ov; bi = oi; }
        }
        if (lane == 0) { rv[w] = bv; ri[w] = bi; }
        __syncthreads();
        if (w == 0) {
            float v = rv[lane]; int vi = ri[lane];
            #pragma unroll
            for (int o = 16; o; o >>= 1) {
                float ov = __shfl_xor_sync(0xffffffffu, v, o);
                int   oi = __shfl_xor_sync(0xffffffffu, vi, o);
                if (ov > v || (ov == v && oi < vi)) { v = ov; vi = oi; }
            }
            if (lane == 0) { top_i[sel] = vi; top_v[sel] = v; ss[vi] = -INFINITY; }
        }
        __syncthreads();
    }

    for (int i = t; i < Mm*Dd; i += 1024) {
        int sel = i / Dd, d = i % Dd;
        int idx = top_i[sel];
        float alpha = expf(top_v[sel] - vmax) * inv;
        float mk = node_mask[(size_t)b*Nn + idx] ? 1.f : 0.f;
        float hv = g_h[((size_t)b*Nn + idx)*Dd + d] * mk;
        out[((size_t)b*Mm + sel)*Dd + d] = hv * alpha;
    }
    float m0 = node_mask[(size_t)b*Nn] ? 1.f : 0.f;
    for (int d = t; d < Dd; d += 1024)
        out[(size_t)Bk*Mm*Dd + (size_t)b*Dd + d] = g_h[((size_t)b*Nn)*Dd + d] * m0;
}

// ---------------- launch ----------------
extern "C" void kernel_launch(void* const* d_in, const int* in_sizes, int n_in,
                              void* d_out, int out_size)
{
    (void)in_sizes; (void)n_in; (void)out_size;
    const int*   dists      = (const int*)d_in[0];
    const int*   edge_index = (const int*)d_in[1];
    const int*   rels       = (const int*)d_in[2];
    const int*   node_mask  = (const int*)d_in[3];
    const int*   edge_mask  = (const int*)d_in[4];
    const float* rq         = (const float*)d_in[5];
    const float* conf       = (const float*)d_in[6];
    const float* noise      = (const float*)d_in[7];
    const float* dist_table = (const float*)d_in[8];
    const float* rel_table  = (const float*)d_in[9];
    const float* msg_W      = (const float*)d_in[10];
    const float* msg_b      = (const float*)d_in[11];
    const float* upd_W      = (const float*)d_in[12];
    const float* upd_b      = (const float*)d_in[13];
    const float* att_W      = (const float*)d_in[14];
    const float* att_b      = (const float*)d_in[15];
    float* out = (float*)d_out;

    cudaFuncSetAttribute(edge_hmma_kernel, cudaFuncAttributeMaxDynamicSharedMemorySize, ESMEM);
    cudaFuncSetAttribute(update_hmma_kernel, cudaFuncAttributeMaxDynamicSharedMemorySize, (int)USMEM);

    int total4 = Bk*Nn*Dd/4;
    prep_kernel<<<(total4 + 255)/256, 256>>>(dists, noise, dist_table);
    prep_misc<<<(AUXN + WTSN + TBLN + 255)/256, 256>>>(conf, dist_table, rel_table, msg_W, upd_W);

    for (int l = 0; l < Ll; l++) {
        edge_hmma_kernel<<<Bk*(Ee/64), 256, ESMEM>>>(
            l, edge_index, rels, edge_mask, dists, rel_table, msg_b + (size_t)l*Dd);
        update_hmma_kernel<<<2*Bk*Nn/128, 256, USMEM>>>(l, (l != Ll-1) ? 1 : 0, upd_b + (size_t)l*Dd);
    }

    score_kernel<<<Bk*Nn/8, 256>>>(att_W, att_b, node_mask, rq);
    topk_kernel<<<Bk, 1024>>>(node_mask, out);
}

// round 16
// speedup vs baseline: 1.0298x; 1.0298x over previous
#include <cuda_runtime.h>
#include <cuda_fp16.h>
#include <math.h>
#include <stdint.h>

#define Bk 8
#define Nn 8192
#define Ee 16384
#define Dd 128
#define Mm 20
#define Ll 3
#define Rr 200

// ---- edge kernel geometry (validated R9..R14: 128 edges x 128 out) ----
#define CH 32
#define ESTR 40
#define TILE_H (128*ESTR)
#define STAGE_H (4*TILE_H)
#define ESMEM (2*STAGE_H*2)
#define NCH 12

// ---- update kernel geometry (validated R14: N-split) ----
#define USTR 72
#define UAT (128*USTR)
#define UBT (64*USTR)
#define UB_BASE (2*UAT)
#define USMEM ((2*UAT + 4*UBT)*2)

// -------- device scratch --------
__device__ float g_h[(size_t)Bk*Nn*Dd];
__device__ float g_aggr[Ll][(size_t)Bk*Nn*Dd];
__device__ float g_scores[Bk*Nn];
__device__ float g_tblD[Ll*10*Dd];
__device__ float g_tblR[Ll*Rr*Dd];
__device__ __half g_hhi[(size_t)Bk*Nn*Dd],  g_hlo[(size_t)Bk*Nn*Dd];
__device__ __half g_confhi[(size_t)Bk*Ee*Dd], g_conflo[(size_t)Bk*Ee*Dd];
__device__ __half g_msgWhi[(size_t)Ll*20*128*32], g_msgWlo[(size_t)Ll*20*128*32];
__device__ __half g_updWhi[(size_t)Ll*2*128*64],  g_updWlo[(size_t)Ll*2*128*64];

__device__ __forceinline__ uint32_t smem_u32(const void* p){
    uint32_t a;
    asm("{ .reg .u64 t; cvta.to.shared.u64 t, %1; cvt.u32.u64 %0, t; }" : "=r"(a) : "l"(p));
    return a;
}
__device__ __forceinline__ void cpa16(uint32_t dst, const void* src){
    asm volatile("cp.async.cg.shared.global [%0], [%1], 16;" :: "r"(dst), "l"(src));
}
#define CP_COMMIT() asm volatile("cp.async.commit_group;" ::: "memory")

#define LDSM4(r, addr) \
    asm volatile("ldmatrix.sync.aligned.m8n8.x4.shared.b16 {%0,%1,%2,%3}, [%4];" \
        : "=r"((r)[0]), "=r"((r)[1]), "=r"((r)[2]), "=r"((r)[3]) : "r"(addr))

#define MMA_F16(c, a, b0, b1) \
    asm volatile("mma.sync.aligned.m16n8k16.row.col.f32.f16.f16.f32 " \
        "{%0,%1,%2,%3}, {%4,%5,%6,%7}, {%8,%9}, {%0,%1,%2,%3};" \
        : "+f"((c)[0]), "+f"((c)[1]), "+f"((c)[2]), "+f"((c)[3]) \
        : "r"((a)[0]), "r"((a)[1]), "r"((a)[2]), "r"((a)[3]), "r"(b0), "r"(b1))

__device__ __forceinline__ void pack2(float2 v, uint32_t& hi, uint32_t& lo){
    __half h0 = __float2half_rn(v.x), h1 = __float2half_rn(v.y);
    __half2 H = __halves2half2(h0, h1);
    __half2 L = __halves2half2(__float2half_rn(v.x - __half2float(h0)),
                               __float2half_rn(v.y - __half2float(h1)));
    hi = *(uint32_t*)&H; lo = *(uint32_t*)&L;
}

// ---------------- fused prep: EVERYTHING in one launch ----------------
#define NODE4 (Bk*Nn*Dd/4)
#define AUXN (Bk*Ee*Dd/4)
#define MSGTOT (Ll*5*Dd*Dd)
#define WTSN (MSGTOT + Ll*Dd*Dd)
#define TBLN (Ll*(10+Rr)*Dd)
#define SC4  (Bk*Nn/4)
#define PREP_TOT (NODE4 + AUXN + WTSN + TBLN + SC4)

__global__ void prep_all(const int* __restrict__ dists,
                         const float* __restrict__ noise,
                         const float* __restrict__ dtab,
                         const float* __restrict__ conf,
                         const float* __restrict__ rel_table,
                         const float* __restrict__ msgW,
                         const float* __restrict__ updW)
{
    int i = blockIdx.x * blockDim.x + threadIdx.x;
    if (i < NODE4) {
        int node = i >> 5;
        int c = i & 31;
        int di = dists[node];
        di = di < 0 ? 0 : (di > 9 ? 9 : di);
        float4 dv = __ldg(((const float4*)(dtab + (size_t)di*Dd)) + c);
        float4 nz = ((const float4*)noise)[i];
        float4 h;
        h.x = dv.x + 0.1f*nz.x; h.y = dv.y + 0.1f*nz.y;
        h.z = dv.z + 0.1f*nz.z; h.w = dv.w + 0.1f*nz.w;
        ((float4*)g_h)[i]  = h;
        float4 z = make_float4(0.f, 0.f, 0.f, 0.f);
        ((float4*)g_aggr[0])[i] = z;
        ((float4*)g_aggr[1])[i] = z;
        ((float4*)g_aggr[2])[i] = z;
        uint32_t hiA, loA, hiB, loB;
        pack2(make_float2(h.x, h.y), hiA, loA);
        pack2(make_float2(h.z, h.w), hiB, loB);
        ((uint32_t*)g_hhi)[2*i] = hiA; ((uint32_t*)g_hhi)[2*i+1] = hiB;
        ((uint32_t*)g_hlo)[2*i] = loA; ((uint32_t*)g_hlo)[2*i+1] = loB;
        return;
    }
    int a = i - NODE4;
    if (a < AUXN) {
        float4 v = ((const float4*)conf)[a];
        int base = a*4;
        uint32_t hiA, loA, hiB, loB;
        pack2(make_float2(v.x, v.y), hiA, loA);
        pack2(make_float2(v.z, v.w), hiB, loB);
        *(uint32_t*)(g_confhi + base)     = hiA;
        *(uint32_t*)(g_confhi + base + 2) = hiB;
        *(uint32_t*)(g_conflo + base)     = loA;
        *(uint32_t*)(g_conflo + base + 2) = loB;
        return;
    }
    int j = a - AUXN;
    if (j < WTSN) {
        if (j < MSGTOT) {
            int l = j / (640*128);
            int k = (j / 128) % 640;
            int n = j & 127;
            int ch = k >> 5, kk = k & 31;
            float w = msgW[j];
            __half hi = __float2half_rn(w);
            __half lo = __float2half_rn(w - __half2float(hi));
            size_t o = (((size_t)(l*20 + ch))*128 + n)*32 + kk;
            g_msgWhi[o] = hi; g_msgWlo[o] = lo;
        } else {
            int q = j - MSGTOT;
            int l = q / (128*128);
            int k = (q / 128) % 128;
            int n = q & 127;
            int ch = k >> 6, kk = k & 63;
            float w = updW[q];
            __half hi = __float2half_rn(w);
            __half lo = __float2half_rn(w - __half2float(hi));
            size_t o = (((size_t)(l*2 + ch))*128 + n)*64 + kk;
            g_updWhi[o] = hi; g_updWlo[o] = lo;
        }
        return;
    }
    int t = j - WTSN;
    if (t < TBLN) {
        int n = t & 127;
        int row = (t >> 7) % (10+Rr);
        int l = t / ((10+Rr)*Dd);
        const float* Wl = msgW + (size_t)l*640*128;
        const float* vec; const float* w; float* dst;
        if (row < 10) {
            vec = dtab + row*Dd;
            w = Wl + (size_t)2*128*128;
            dst = g_tblD + (l*10 + row)*Dd + n;
        } else {
            vec = rel_table + (size_t)(row-10)*Dd;
            w = Wl + (size_t)3*128*128;
            dst = g_tblR + ((size_t)l*Rr + (row-10))*Dd + n;
        }
        float s0=0.f, s1=0.f, s2=0.f, s3=0.f;
        #pragma unroll
        for (int k = 0; k < 128; k += 4) {
            s0 = fmaf(vec[k],   __ldg(w + (size_t)k*128 + n),     s0);
            s1 = fmaf(vec[k+1], __ldg(w + (size_t)(k+1)*128 + n), s1);
            s2 = fmaf(vec[k+2], __ldg(w + (size_t)(k+2)*128 + n), s2);
            s3 = fmaf(vec[k+3], __ldg(w + (size_t)(k+3)*128 + n), s3);
        }
        *dst = (s0 + s1) + (s2 + s3);
        return;
    }
    int s = t - TBLN;
    if (s < SC4) {
        ((float4*)g_scores)[s] = make_float4(0.f, 0.f, 0.f, 0.f);
    }
}

// ---------------- edge GEMM (validated R14, byte-identical) ----------------
__global__ void __launch_bounds__(256, 2)
edge_hmma_kernel(int layer,
                 const int* __restrict__ edge_index,
                 const int* __restrict__ rels,
                 const int* __restrict__ edge_mask,
                 const int* __restrict__ dists,
                 const float* __restrict__ rel_table,
                 const float* __restrict__ bias)
{
    extern __shared__ __half sm[];
    __shared__ int   s_src[128], s_tgt[128], s_rel[128], s_di[128];
    __shared__ float s_em[128], s_bias[128];

    int tid = threadIdx.x, wid = tid >> 5, lane = tid & 31;
    int b  = blockIdx.x >> 7;
    int e0 = (blockIdx.x & 127) << 7;
    size_t bN = (size_t)b * Nn;

    if (tid < 128) {
        int e = e0 + tid;
        int src = edge_index[(size_t)b*2*Ee + e];
        s_src[tid] = src;
        s_tgt[tid] = edge_index[(size_t)b*2*Ee + Ee + e];
        s_rel[tid] = rels[(size_t)b*Ee + e];
        s_em[tid]  = edge_mask[(size_t)b*Ee + e] ? 1.f : 0.f;
        s_bias[tid] = bias[tid];
        int di = dists[bN + src];
        s_di[tid] = di < 0 ? 0 : (di > 9 ? 9 : di);
    }
    __syncthreads();

    uint32_t smb = smem_u32(sm);
    int wm = wid & 3, wn = wid >> 2;
    int g = lane >> 2, t4 = lane & 3;

    float acc[2][8][4];
    #pragma unroll
    for (int i = 0; i < 2; i++)
        #pragma unroll
        for (int j = 0; j < 8; j++)
            #pragma unroll
            for (int q = 0; q < 4; q++) acc[i][j][q] = 0.f;

    auto issue = [&](int c, int st){
        uint32_t sb = smb + (uint32_t)(st*STAGE_H)*2;
        int wc = (c < 4) ? (4 + c) : ((c < 8) ? (12 + c) : (c - 8));
        const __half* wh = g_msgWhi + ((size_t)(layer*20 + wc))*4096;
        const __half* wl = g_msgWlo + ((size_t)(layer*20 + wc))*4096;
        #pragma unroll
        for (int r = 0; r < 2; r++){
            int idx = tid + r*256;
            int n = idx >> 2, f = idx & 3;
            uint32_t d = sb + (uint32_t)(2*TILE_H + n*ESTR + f*8)*2;
            cpa16(d,              wh + n*32 + f*8);
            cpa16(d + TILE_H*2,   wl + n*32 + f*8);
        }
        if (c < 8){
            int koff = (c & 3)*CH;
            #pragma unroll
            for (int r = 0; r < 2; r++){
                int idx = tid + r*256;
                int e = idx >> 2, q = idx & 3;
                size_t rowoff;
                const __half *ph, *pl;
                if (c < 4) { rowoff = (bN + s_src[e])*Dd; ph = g_hhi; pl = g_hlo; }
                else       { rowoff = ((size_t)b*Ee + e0 + e)*Dd; ph = g_confhi; pl = g_conflo; }
                uint32_t d = sb + (uint32_t)(e*ESTR + q*8)*2;
                cpa16(d,            ph + rowoff + koff + q*8);
                cpa16(d + TILE_H*2, pl + rowoff + koff + q*8);
            }
        }
    };
    auto fill0 = [&](int c, int st){
        __half* base = sm + st*STAGE_H;
        int koff = (c - 8)*CH;
        #pragma unroll
        for (int r = 0; r < 2; r++){
            int idx = tid + r*256;
            int e = idx >> 2, q = idx & 3;
            const float* hp = g_h + (bN + s_src[e])*Dd + koff + q*8;
            const float* rp = rel_table + (size_t)s_rel[e]*Dd + koff + q*8;
            float4 h1 = *(const float4*)hp, h2 = *(const float4*)(hp + 4);
            float4 r1 = *(const float4*)rp, r2 = *(const float4*)(rp + 4);
            float pr[8] = {h1.x*r1.x, h1.y*r1.y, h1.z*r1.z, h1.w*r1.w,
                           h2.x*r2.x, h2.y*r2.y, h2.z*r2.z, h2.w*r2.w};
            __half hh[8], ll[8];
            #pragma unroll
            for (int u = 0; u < 8; u++){
                hh[u] = __float2half_rn(pr[u]);
                ll[u] = __float2half_rn(pr[u] - __half2float(hh[u]));
            }
            *(uint4*)(base + e*ESTR + q*8)          = *(uint4*)hh;
            *(uint4*)(base + TILE_H + e*ESTR + q*8) = *(uint4*)ll;
        }
    };

    issue(0, 0); CP_COMMIT();

    for (int c = 0; c < NCH; c++){
        int st = c & 1, nst = st ^ 1;
        if (c + 1 < NCH){
            issue(c + 1, nst);
            if (c + 1 >= 8) fill0(c + 1, nst);
            CP_COMMIT();
            asm volatile("cp.async.wait_group 1;" ::: "memory");
        } else {
            asm volatile("cp.async.wait_group 0;" ::: "memory");
        }
        __syncthreads();

        uint32_t sb = smb + (uint32_t)(st*STAGE_H)*2;
        #pragma unroll
        for (int k16 = 0; k16 < 2; k16++){
            int kb = k16*16;
            uint32_t ah[2][4], al[2][4];
            #pragma unroll
            for (int i = 0; i < 2; i++){
                uint32_t a = sb + (uint32_t)((wm*32 + i*16 + (lane & 15))*ESTR + kb + (lane >> 4)*8)*2;
                LDSM4(ah[i], a);
                LDSM4(al[i], a + TILE_H*2);
            }
            uint32_t bh[2][4], bl[2][4];
            {
                uint32_t bb = sb + (uint32_t)(2*TILE_H + (wn*64 + (lane & 15))*ESTR + kb + (lane >> 4)*8)*2;
                LDSM4(bh[0], bb);
                LDSM4(bl[0], bb + TILE_H*2);
            }
            #pragma unroll
            for (int jp = 0; jp < 4; jp++){
                int cur = jp & 1, nxt = cur ^ 1;
                if (jp < 3){
                    uint32_t bb = sb + (uint32_t)(2*TILE_H + (wn*64 + (jp+1)*16 + (lane & 15))*ESTR + kb + (lane >> 4)*8)*2;
                    LDSM4(bh[nxt], bb);
                    LDSM4(bl[nxt], bb + TILE_H*2);
                }
                MMA_F16(acc[0][jp*2+0], ah[0], bh[cur][0], bh[cur][2]);
                MMA_F16(acc[0][jp*2+1], ah[0], bh[cur][1], bh[cur][3]);
                MMA_F16(acc[1][jp*2+0], ah[1], bh[cur][0], bh[cur][2]);
                MMA_F16(acc[1][jp*2+1], ah[1], bh[cur][1], bh[cur][3]);
                MMA_F16(acc[0][jp*2+0], ah[0], bl[cur][0], bl[cur][2]);
                MMA_F16(acc[0][jp*2+1], ah[0], bl[cur][1], bl[cur][3]);
                MMA_F16(acc[1][jp*2+0], ah[1], bl[cur][0], bl[cur][2]);
                MMA_F16(acc[1][jp*2+1], ah[1], bl[cur][1], bl[cur][3]);
                MMA_F16(acc[0][jp*2+0], al[0], bh[cur][0], bh[cur][2]);
                MMA_F16(acc[0][jp*2+1], al[0], bh[cur][1], bh[cur][3]);
                MMA_F16(acc[1][jp*2+0], al[1], bh[cur][0], bh[cur][2]);
                MMA_F16(acc[1][jp*2+1], al[1], bh[cur][1], bh[cur][3]);
            }
        }
        __syncthreads();
    }

    float* aggr = g_aggr[layer];
    #pragma unroll
    for (int i = 0; i < 2; i++) {
        #pragma unroll
        for (int half = 0; half < 2; half++) {
            int row = wm*32 + i*16 + g + half*8;
            if (s_em[row] != 0.f) {
                const float* tD = g_tblD + (layer*10 + s_di[row])*Dd;
                const float* tR = g_tblR + ((size_t)layer*Rr + s_rel[row])*Dd;
                float* dst = aggr + (bN + s_tgt[row])*Dd;
                #pragma unroll
                for (int j = 0; j < 8; j++) {
                    int col = wn*64 + j*8 + t4*2;
                    float add0 = s_bias[col]   + __ldg(tD + col)     + __ldg(tR + col);
                    float add1 = s_bias[col+1] + __ldg(tD + col + 1) + __ldg(tR + col + 1);
                    float v0 = acc[i][j][half*2+0] + add0;
                    float v1 = acc[i][j][half*2+1] + add1;
                    if (v0 > 0.f) atomicAdd(dst + col,     v0);
                    if (v1 > 0.f) atomicAdd(dst + col + 1, v1);
                }
            }
        }
    }
}

// ---------------- node update GEMM (validated R14) + fused score on last layer ----------------
__global__ void __launch_bounds__(256, 3)
update_hmma_kernel(int layer, int write_split,
                   const float* __restrict__ bias,
                   const float* __restrict__ attW)
{
    extern __shared__ __half sm[];
    __shared__ float s_bias[128];

    int tid = threadIdx.x, wid = tid >> 5, lane = tid & 31;
    size_t r0 = (size_t)(blockIdx.x >> 1) * 128;
    int nb = blockIdx.x & 1;
    uint32_t smb = smem_u32(sm);

    {
        const __half* wh = g_updWhi + (size_t)layer*2*8192 + nb*64*64;
        const __half* wl = g_updWlo + (size_t)layer*2*8192 + nb*64*64;
        #pragma unroll
        for (int it = 0; it < 4; it++) {
            int idx = tid + it*256;
            int c = idx >> 9, r = idx & 511;
            int n = r >> 3, q = r & 7;
            uint32_t dhi = smb + (uint32_t)(UB_BASE + 2*c*UBT + n*USTR + q*8)*2;
            cpa16(dhi,           wh + (size_t)c*8192 + n*64 + q*8);
            cpa16(dhi + UBT*2,   wl + (size_t)c*8192 + n*64 + q*8);
        }
        CP_COMMIT();
    }
    if (tid < 128) s_bias[tid] = bias[tid];

    int wm = wid & 3, wn = wid >> 2;
    int g = lane >> 2, t4 = lane & 3;
    const float* aggr = g_aggr[layer];

    float acc[2][4][4];
    #pragma unroll
    for (int i = 0; i < 2; i++)
        #pragma unroll
        for (int j = 0; j < 4; j++)
            #pragma unroll
            for (int q = 0; q < 4; q++) acc[i][j][q] = 0.f;

    for (int c = 0; c < 2; c++) {
        int koff = c*64;
        #pragma unroll
        for (int it = 0; it < 8; it++) {
            int idx = tid + it*256;
            int row = idx >> 4, q = idx & 15;
            float4 v = *(const float4*)(aggr + (r0 + row)*Dd + koff + q*4);
            __half h0 = __float2half_rn(v.x), h1 = __float2half_rn(v.y);
            __half h2 = __float2half_rn(v.z), h3 = __float2half_rn(v.w);
            int ho = row*USTR + q*4;
            *(__half2*)(sm + ho)           = __halves2half2(h0, h1);
            *(__half2*)(sm + ho + 2)       = __halves2half2(h2, h3);
            *(__half2*)(sm + UAT + ho)     = __halves2half2(__float2half_rn(v.x-__half2float(h0)), __float2half_rn(v.y-__half2float(h1)));
            *(__half2*)(sm + UAT + ho + 2) = __halves2half2(__float2half_rn(v.z-__half2float(h2)), __float2half_rn(v.w-__half2float(h3)));
        }
        if (c == 0) asm volatile("cp.async.wait_group 0;" ::: "memory");
        __syncthreads();

        uint32_t bbase = smb + (uint32_t)(UB_BASE + 2*c*UBT)*2;
        #pragma unroll
        for (int k16 = 0; k16 < 4; k16++) {
            int kb = k16*16;
            uint32_t ahi[2][4], alo[2][4];
            #pragma unroll
            for (int i = 0; i < 2; i++) {
                uint32_t aadr = smb + (uint32_t)((wm*32 + i*16 + (lane & 15))*USTR + kb + (lane >> 4)*8)*2;
                LDSM4(ahi[i], aadr);
                LDSM4(alo[i], aadr + UAT*2);
            }
            #pragma unroll
            for (int jp = 0; jp < 2; jp++) {
                uint32_t bb = bbase + (uint32_t)((wn*32 + jp*16 + (lane & 15))*USTR + kb + (lane >> 4)*8)*2;
                uint32_t bh[4], bl[4];
                LDSM4(bh, bb);
                LDSM4(bl, bb + UBT*2);
                MMA_F16(acc[0][jp*2+0], ahi[0], bh[0], bh[2]);
                MMA_F16(acc[0][jp*2+1], ahi[0], bh[1], bh[3]);
                MMA_F16(acc[1][jp*2+0], ahi[1], bh[0], bh[2]);
                MMA_F16(acc[1][jp*2+1], ahi[1], bh[1], bh[3]);
                MMA_F16(acc[0][jp*2+0], ahi[0], bl[0], bl[2]);
                MMA_F16(acc[0][jp*2+1], ahi[0], bl[1], bl[3]);
                MMA_F16(acc[1][jp*2+0], ahi[1], bl[0], bl[2]);
                MMA_F16(acc[1][jp*2+1], ahi[1], bl[1], bl[3]);
                MMA_F16(acc[0][jp*2+0], alo[0], bh[0], bh[2]);
                MMA_F16(acc[0][jp*2+1], alo[0], bh[1], bh[3]);
                MMA_F16(acc[1][jp*2+0], alo[1], bh[0], bh[2]);
                MMA_F16(acc[1][jp*2+1], alo[1], bh[1], bh[3]);
            }
        }
        __syncthreads();
    }

    // epilogue: h += d + bias; split writes if more layers; fused score partials on last layer
    #pragma unroll
    for (int i = 0; i < 2; i++) {
        #pragma unroll
        for (int half = 0; half < 2; half++) {
            int row = wm*32 + i*16 + g + half*8;
            size_t gro = (r0 + row)*Dd;
            float* hp = g_h + gro;
            float part = 0.f;
            #pragma unroll
            for (int j = 0; j < 4; j++) {
                int col = nb*64 + wn*32 + j*8 + t4*2;
                float2 hv = *(float2*)(hp + col);
                float v0 = hv.x + acc[i][j][half*2+0] + s_bias[col];
                float v1 = hv.y + acc[i][j][half*2+1] + s_bias[col+1];
                *(float2*)(hp + col) = make_float2(v0, v1);
                if (write_split) {
                    uint32_t hi, lo;
                    pack2(make_float2(v0, v1), hi, lo);
                    *(uint32_t*)(g_hhi + gro + col) = hi;
                    *(uint32_t*)(g_hlo + gro + col) = lo;
                } else {
                    part = fmaf(v0, __ldg(attW + col), part);
                    part = fmaf(v1, __ldg(attW + col + 1), part);
                }
            }
            if (!write_split) atomicAdd(g_scores + r0 + row, part);
        }
    }
}

// ---------------- softmax + top-20 + output (score finish fused in) ----------------
__global__ void __launch_bounds__(1024)
topk_kernel(const int* __restrict__ node_mask, float* __restrict__ out,
            const float* __restrict__ attW, const float* __restrict__ attb,
            const float* __restrict__ rq)
{
    __shared__ float ss[Nn];
    __shared__ float rv[32];
    __shared__ int   ri[32];
    __shared__ float s_red;
    __shared__ int   top_i[Mm];
    __shared__ float top_v[Mm];

    int b = blockIdx.x;
    int t = threadIdx.x;
    int w = t >> 5, lane = t & 31;

    // rq dot attW[128:256] + attb  (warp 0, redundant across lanes is fine)
    if (w == 0) {
        float s = 0.f;
        #pragma unroll
        for (int i = 0; i < 4; i++) {
            int d = lane + i*32;
            s = fmaf(rq[b*Dd + d], __ldg(attW + Dd + d), s);
        }
        #pragma unroll
        for (int o = 16; o; o >>= 1) s += __shfl_xor_sync(0xffffffffu, s, o);
        if (lane == 0) s_red = s + attb[0];
    }
    __syncthreads();
    float qadd = s_red;

    for (int i = t; i < Nn; i += 1024) {
        float s = g_scores[(size_t)b*Nn + i] + qadd;
        s = (s > 0.f) ? s : 0.01f * s;
        if (!node_mask[(size_t)b*Nn + i]) s = -1e9f;
        ss[i] = s;
    }
    __syncthreads();

    float m = -INFINITY;
    for (int i = t; i < Nn; i += 1024) m = fmaxf(m, ss[i]);
    #pragma unroll
    for (int o = 16; o; o >>= 1) m = fmaxf(m, __shfl_xor_sync(0xffffffffu, m, o));
    if (lane == 0) rv[w] = m;
    __syncthreads();
    if (w == 0) {
        float v = rv[lane];
        #pragma unroll
        for (int o = 16; o; o >>= 1) v = fmaxf(v, __shfl_xor_sync(0xffffffffu, v, o));
        if (lane == 0) s_red = v;
    }
    __syncthreads();
    float vmax = s_red;

    float sum = 0.f;
    for (int i = t; i < Nn; i += 1024) sum += expf(ss[i] - vmax);
    #pragma unroll
    for (int o = 16; o; o >>= 1) sum += __shfl_xor_sync(0xffffffffu, sum, o);
    if (lane == 0) rv[w] = sum;
    __syncthreads();
    if (w == 0) {
        float v = rv[lane];
        #pragma unroll
        for (int o = 16; o; o >>= 1) v += __shfl_xor_sync(0xffffffffu, v, o);
        if (lane == 0) s_red = v;
    }
    __syncthreads();
    float inv = 1.f / s_red;

    for (int sel = 0; sel < Mm; sel++) {
        float bv = -INFINITY; int bi = Nn;
        for (int i = t; i < Nn; i += 1024) {
            float v = ss[i];
            if (v > bv) { bv = v; bi = i; }
        }
        #pragma unroll
        for (int o = 16; o; o >>= 1) {
            float ov = __shfl_xor_sync(0xffffffffu, bv, o);
            int   oi = __shfl_xor_sync(0xffffffffu, bi, o);
            if (ov > bv || (ov == bv && oi < bi)) { bv = ov; bi = oi; }
        }
        if (lane == 0) { rv[w] = bv; ri[w] = bi; }
        __syncthreads();
        if (w == 0) {
            float v = rv[lane]; int vi = ri[lane];
            #pragma unroll
            for (int o = 16; o; o >>= 1) {
                float ov = __shfl_xor_sync(0xffffffffu, v, o);
                int   oi = __shfl_xor_sync(0xffffffffu, vi, o);
                if (ov > v || (ov == v && oi < vi)) { v = ov; vi = oi; }
            }
            if (lane == 0) { top_i[sel] = vi; top_v[sel] = v; ss[vi] = -INFINITY; }
        }
        __syncthreads();
    }

    for (int i = t; i < Mm*Dd; i += 1024) {
        int sel = i / Dd, d = i % Dd;
        int idx = top_i[sel];
        float alpha = expf(top_v[sel] - vmax) * inv;
        float mk = node_mask[(size_t)b*Nn + idx] ? 1.f : 0.f;
        float hv = g_h[((size_t)b*Nn + idx)*Dd + d] * mk;
        out[((size_t)b*Mm + sel)*Dd + d] = hv * alpha;
    }
    float m0 = node_mask[(size_t)b*Nn] ? 1.f : 0.f;
    for (int d = t; d < Dd; d += 1024)
        out[(size_t)Bk*Mm*Dd + (size_t)b*Dd + d] = g_h[((size_t)b*Nn)*Dd + d] * m0;
}

// ---------------- launch ----------------
extern "C" void kernel_launch(void* const* d_in, const int* in_sizes, int n_in,
                              void* d_out, int out_size)
{
    (void)in_sizes; (void)n_in; (void)out_size;
    const int*   dists      = (const int*)d_in[0];
    const int*   edge_index = (const int*)d_in[1];
    const int*   rels       = (const int*)d_in[2];
    const int*   node_mask  = (const int*)d_in[3];
    const int*   edge_mask  = (const int*)d_in[4];
    const float* rq         = (const float*)d_in[5];
    const float* conf       = (const float*)d_in[6];
    const float* noise      = (const float*)d_in[7];
    const float* dist_table = (const float*)d_in[8];
    const float* rel_table  = (const float*)d_in[9];
    const float* msg_W      = (const float*)d_in[10];
    const float* msg_b      = (const float*)d_in[11];
    const float* upd_W      = (const float*)d_in[12];
    const float* upd_b      = (const float*)d_in[13];
    const float* att_W      = (const float*)d_in[14];
    const float* att_b      = (const float*)d_in[15];
    float* out = (float*)d_out;

    cudaFuncSetAttribute(edge_hmma_kernel, cudaFuncAttributeMaxDynamicSharedMemorySize, ESMEM);
    cudaFuncSetAttribute(update_hmma_kernel, cudaFuncAttributeMaxDynamicSharedMemorySize, (int)USMEM);

    prep_all<<<(PREP_TOT + 255)/256, 256>>>(dists, noise, dist_table, conf,
                                            rel_table, msg_W, upd_W);

    for (int l = 0; l < Ll; l++) {
        edge_hmma_kernel<<<Bk*(Ee/128), 256, ESMEM>>>(
            l, edge_index, rels, edge_mask, dists, rel_table, msg_b + (size_t)l*Dd);
        update_hmma_kernel<<<2*Bk*Nn/128, 256, USMEM>>>(
            l, (l != Ll-1) ? 1 : 0, upd_b + (size_t)l*Dd, att_W);
    }

    topk_kernel<<<Bk, 1024>>>(node_mask, out, att_W, att_b, rq);
}

// round 17
// speedup vs baseline: 1.0940x; 1.0624x over previous
#include <cuda_runtime.h>
#include <cuda_fp16.h>
#include <math.h>
#include <stdint.h>

#define Bk 8
#define Nn 8192
#define Ee 16384
#define Dd 128
#define Mm 20
#define Ll 3
#define Rr 200

// ---- edge kernel geometry (validated R9..R16) ----
#define CH 32
#define ESTR 40
#define TILE_H (128*ESTR)
#define STAGE_H (4*TILE_H)
#define ESMEM (2*STAGE_H*2)
#define NCH 12

// ---- update kernel geometry (validated R14) ----
#define USTR 72
#define UAT (128*USTR)
#define UBT (64*USTR)
#define UB_BASE (2*UAT)
#define USMEM ((2*UAT + 4*UBT)*2)

// -------- device scratch --------
__device__ float g_h[(size_t)Bk*Nn*Dd];
__device__ float g_aggr[Ll][(size_t)Bk*Nn*Dd];
__device__ float g_scores[Bk*Nn];
__device__ float g_tblD[Ll*10*Dd];
__device__ float g_tblR[Ll*Rr*Dd];
__device__ __half g_hhi[(size_t)Bk*Nn*Dd],  g_hlo[(size_t)Bk*Nn*Dd];
__device__ __half g_confhi[(size_t)Bk*Ee*Dd], g_conflo[(size_t)Bk*Ee*Dd];
__device__ __half g_msgWhi[(size_t)Ll*20*128*32], g_msgWlo[(size_t)Ll*20*128*32];
__device__ __half g_updWhi[(size_t)Ll*2*128*64],  g_updWlo[(size_t)Ll*2*128*64];

__device__ __forceinline__ uint32_t smem_u32(const void* p){
    uint32_t a;
    asm("{ .reg .u64 t; cvta.to.shared.u64 t, %1; cvt.u32.u64 %0, t; }" : "=r"(a) : "l"(p));
    return a;
}
__device__ __forceinline__ void cpa16(uint32_t dst, const void* src){
    asm volatile("cp.async.cg.shared.global [%0], [%1], 16;" :: "r"(dst), "l"(src));
}
__device__ __forceinline__ void cpa16_ca(uint32_t dst, const void* src){
    asm volatile("cp.async.ca.shared.global [%0], [%1], 16;" :: "r"(dst), "l"(src));
}
#define CP_COMMIT() asm volatile("cp.async.commit_group;" ::: "memory")

#define LDSM4(r, addr) \
    asm volatile("ldmatrix.sync.aligned.m8n8.x4.shared.b16 {%0,%1,%2,%3}, [%4];" \
        : "=r"((r)[0]), "=r"((r)[1]), "=r"((r)[2]), "=r"((r)[3]) : "r"(addr))

#define MMA_F16(c, a, b0, b1) \
    asm volatile("mma.sync.aligned.m16n8k16.row.col.f32.f16.f16.f32 " \
        "{%0,%1,%2,%3}, {%4,%5,%6,%7}, {%8,%9}, {%0,%1,%2,%3};" \
        : "+f"((c)[0]), "+f"((c)[1]), "+f"((c)[2]), "+f"((c)[3]) \
        : "r"((a)[0]), "r"((a)[1]), "r"((a)[2]), "r"((a)[3]), "r"(b0), "r"(b1))

__device__ __forceinline__ void pack2(float2 v, uint32_t& hi, uint32_t& lo){
    __half h0 = __float2half_rn(v.x), h1 = __float2half_rn(v.y);
    __half2 H = __halves2half2(h0, h1);
    __half2 L = __halves2half2(__float2half_rn(v.x - __half2float(h0)),
                               __float2half_rn(v.y - __half2float(h1)));
    hi = *(uint32_t*)&H; lo = *(uint32_t*)&L;
}

// ---------------- fused prep (validated R16) ----------------
#define NODE4 (Bk*Nn*Dd/4)
#define AUXN (Bk*Ee*Dd/4)
#define MSGTOT (Ll*5*Dd*Dd)
#define WTSN (MSGTOT + Ll*Dd*Dd)
#define TBLN (Ll*(10+Rr)*Dd)
#define SC4  (Bk*Nn/4)
#define PREP_TOT (NODE4 + AUXN + WTSN + TBLN + SC4)

__global__ void prep_all(const int* __restrict__ dists,
                         const float* __restrict__ noise,
                         const float* __restrict__ dtab,
                         const float* __restrict__ conf,
                         const float* __restrict__ rel_table,
                         const float* __restrict__ msgW,
                         const float* __restrict__ updW)
{
    int i = blockIdx.x * blockDim.x + threadIdx.x;
    if (i < NODE4) {
        int node = i >> 5;
        int c = i & 31;
        int di = dists[node];
        di = di < 0 ? 0 : (di > 9 ? 9 : di);
        float4 dv = __ldg(((const float4*)(dtab + (size_t)di*Dd)) + c);
        float4 nz = ((const float4*)noise)[i];
        float4 h;
        h.x = dv.x + 0.1f*nz.x; h.y = dv.y + 0.1f*nz.y;
        h.z = dv.z + 0.1f*nz.z; h.w = dv.w + 0.1f*nz.w;
        ((float4*)g_h)[i]  = h;
        float4 z = make_float4(0.f, 0.f, 0.f, 0.f);
        ((float4*)g_aggr[0])[i] = z;
        ((float4*)g_aggr[1])[i] = z;
        ((float4*)g_aggr[2])[i] = z;
        uint32_t hiA, loA, hiB, loB;
        pack2(make_float2(h.x, h.y), hiA, loA);
        pack2(make_float2(h.z, h.w), hiB, loB);
        ((uint32_t*)g_hhi)[2*i] = hiA; ((uint32_t*)g_hhi)[2*i+1] = hiB;
        ((uint32_t*)g_hlo)[2*i] = loA; ((uint32_t*)g_hlo)[2*i+1] = loB;
        return;
    }
    int a = i - NODE4;
    if (a < AUXN) {
        float4 v = ((const float4*)conf)[a];
        int base = a*4;
        uint32_t hiA, loA, hiB, loB;
        pack2(make_float2(v.x, v.y), hiA, loA);
        pack2(make_float2(v.z, v.w), hiB, loB);
        *(uint32_t*)(g_confhi + base)     = hiA;
        *(uint32_t*)(g_confhi + base + 2) = hiB;
        *(uint32_t*)(g_conflo + base)     = loA;
        *(uint32_t*)(g_conflo + base + 2) = loB;
        return;
    }
    int j = a - AUXN;
    if (j < WTSN) {
        if (j < MSGTOT) {
            int l = j / (640*128);
            int k = (j / 128) % 640;
            int n = j & 127;
            int ch = k >> 5, kk = k & 31;
            float w = msgW[j];
            __half hi = __float2half_rn(w);
            __half lo = __float2half_rn(w - __half2float(hi));
            size_t o = (((size_t)(l*20 + ch))*128 + n)*32 + kk;
            g_msgWhi[o] = hi; g_msgWlo[o] = lo;
        } else {
            int q = j - MSGTOT;
            int l = q / (128*128);
            int k = (q / 128) % 128;
            int n = q & 127;
            int ch = k >> 6, kk = k & 63;
            float w = updW[q];
            __half hi = __float2half_rn(w);
            __half lo = __float2half_rn(w - __half2float(hi));
            size_t o = (((size_t)(l*2 + ch))*128 + n)*64 + kk;
            g_updWhi[o] = hi; g_updWlo[o] = lo;
        }
        return;
    }
    int t = j - WTSN;
    if (t < TBLN) {
        int n = t & 127;
        int row = (t >> 7) % (10+Rr);
        int l = t / ((10+Rr)*Dd);
        const float* Wl = msgW + (size_t)l*640*128;
        const float* vec; const float* w; float* dst;
        if (row < 10) {
            vec = dtab + row*Dd;
            w = Wl + (size_t)2*128*128;
            dst = g_tblD + (l*10 + row)*Dd + n;
        } else {
            vec = rel_table + (size_t)(row-10)*Dd;
            w = Wl + (size_t)3*128*128;
            dst = g_tblR + ((size_t)l*Rr + (row-10))*Dd + n;
        }
        float s0=0.f, s1=0.f, s2=0.f, s3=0.f;
        #pragma unroll
        for (int k = 0; k < 128; k += 4) {
            s0 = fmaf(vec[k],   __ldg(w + (size_t)k*128 + n),     s0);
            s1 = fmaf(vec[k+1], __ldg(w + (size_t)(k+1)*128 + n), s1);
            s2 = fmaf(vec[k+2], __ldg(w + (size_t)(k+2)*128 + n), s2);
            s3 = fmaf(vec[k+3], __ldg(w + (size_t)(k+3)*128 + n), s3);
        }
        *dst = (s0 + s1) + (s2 + s3);
        return;
    }
    int s = t - TBLN;
    if (s < SC4) {
        ((float4*)g_scores)[s] = make_float4(0.f, 0.f, 0.f, 0.f);
    }
}

// ---------------- edge GEMM: R16 + hoisted offsets + .ca weights ----------------
__global__ void __launch_bounds__(256, 2)
edge_hmma_kernel(int layer,
                 const int* __restrict__ edge_index,
                 const int* __restrict__ rels,
                 const int* __restrict__ edge_mask,
                 const int* __restrict__ dists,
                 const float* __restrict__ rel_table,
                 const float* __restrict__ bias)
{
    extern __shared__ __half sm[];
    __shared__ int   s_src[128], s_tgt[128], s_rel[128], s_di[128];
    __shared__ float s_em[128], s_bias[128];

    int tid = threadIdx.x, wid = tid >> 5, lane = tid & 31;
    int b  = blockIdx.x >> 7;
    int e0 = (blockIdx.x & 127) << 7;
    size_t bN = (size_t)b * Nn;

    if (tid < 128) {
        int e = e0 + tid;
        int src = edge_index[(size_t)b*2*Ee + e];
        s_src[tid] = src;
        s_tgt[tid] = edge_index[(size_t)b*2*Ee + Ee + e];
        s_rel[tid] = rels[(size_t)b*Ee + e];
        s_em[tid]  = edge_mask[(size_t)b*Ee + e] ? 1.f : 0.f;
        s_bias[tid] = bias[tid];
        int di = dists[bN + src];
        s_di[tid] = di < 0 ? 0 : (di > 9 ? 9 : di);
    }
    __syncthreads();

    uint32_t smb = smem_u32(sm);
    int wm = wid & 3, wn = wid >> 2;
    int g = lane >> 2, t4 = lane & 3;

    // hoisted per-thread gather offsets (two (e,q) slots per thread)
    int ge0 = tid >> 2,          gq0 = tid & 3;
    int ge1 = (tid + 256) >> 2,  gq1 = (tid + 256) & 3;
    uint32_t offH0 = (uint32_t)((bN + s_src[ge0])*Dd) + gq0*8;
    uint32_t offH1 = (uint32_t)((bN + s_src[ge1])*Dd) + gq1*8;
    uint32_t offC0 = (uint32_t)(((size_t)b*Ee + e0 + ge0)*Dd) + gq0*8;
    uint32_t offC1 = (uint32_t)(((size_t)b*Ee + e0 + ge1)*Dd) + gq1*8;
    uint32_t offR0 = (uint32_t)(s_rel[ge0]*Dd) + gq0*8;
    uint32_t offR1 = (uint32_t)(s_rel[ge1]*Dd) + gq1*8;
    uint32_t dst0  = (uint32_t)(ge0*ESTR + gq0*8)*2;
    uint32_t dst1  = (uint32_t)(ge1*ESTR + gq1*8)*2;

    float acc[2][8][4];
    #pragma unroll
    for (int i = 0; i < 2; i++)
        #pragma unroll
        for (int j = 0; j < 8; j++)
            #pragma unroll
            for (int q = 0; q < 4; q++) acc[i][j][q] = 0.f;

    auto issue = [&](int c, int st){
        uint32_t sb = smb + (uint32_t)(st*STAGE_H)*2;
        int wc = (c < 4) ? (4 + c) : ((c < 8) ? (12 + c) : (c - 8));
        const __half* wh = g_msgWhi + ((size_t)(layer*20 + wc))*4096;
        const __half* wl = g_msgWlo + ((size_t)(layer*20 + wc))*4096;
        #pragma unroll
        for (int r = 0; r < 2; r++){
            int idx = tid + r*256;
            int n = idx >> 2, f = idx & 3;
            uint32_t d = sb + (uint32_t)(2*TILE_H + n*ESTR + f*8)*2;
            cpa16_ca(d,              wh + n*32 + f*8);
            cpa16_ca(d + TILE_H*2,   wl + n*32 + f*8);
        }
        if (c < 8){
            uint32_t koff = (c & 3)*CH;
            if (c < 4) {
                cpa16(sb + dst0,            g_hhi + offH0 + koff);
                cpa16(sb + dst0 + TILE_H*2, g_hlo + offH0 + koff);
                cpa16(sb + dst1,            g_hhi + offH1 + koff);
                cpa16(sb + dst1 + TILE_H*2, g_hlo + offH1 + koff);
            } else {
                cpa16(sb + dst0,            g_confhi + offC0 + koff);
                cpa16(sb + dst0 + TILE_H*2, g_conflo + offC0 + koff);
                cpa16(sb + dst1,            g_confhi + offC1 + koff);
                cpa16(sb + dst1 + TILE_H*2, g_conflo + offC1 + koff);
            }
        }
    };
    auto fill0 = [&](int c, int st){
        uint32_t base = smb + (uint32_t)(st*STAGE_H)*2;
        uint32_t koff = (c - 8)*CH;
        #pragma unroll
        for (int r = 0; r < 2; r++){
            uint32_t offH = r ? offH1 : offH0;
            uint32_t offR = r ? offR1 : offR0;
            uint32_t dst  = r ? dst1  : dst0;
            const float* hp = g_h + offH + koff;
            const float* rp = rel_table + offR + koff;
            float4 h1 = *(const float4*)hp, h2 = *(const float4*)(hp + 4);
            float4 r1 = *(const float4*)rp, r2 = *(const float4*)(rp + 4);
            float pr[8] = {h1.x*r1.x, h1.y*r1.y, h1.z*r1.z, h1.w*r1.w,
                           h2.x*r2.x, h2.y*r2.y, h2.z*r2.z, h2.w*r2.w};
            __half hh[8], ll[8];
            #pragma unroll
            for (int u = 0; u < 8; u++){
                hh[u] = __float2half_rn(pr[u]);
                ll[u] = __float2half_rn(pr[u] - __half2float(hh[u]));
            }
            *(uint4*)(sm + (dst>>1) + (uint32_t)(st*STAGE_H))          = *(uint4*)hh;
            *(uint4*)(sm + (dst>>1) + (uint32_t)(st*STAGE_H) + TILE_H) = *(uint4*)ll;
            (void)base;
        }
    };

    issue(0, 0); CP_COMMIT();

    for (int c = 0; c < NCH; c++){
        int st = c & 1, nst = st ^ 1;
        if (c + 1 < NCH){
            issue(c + 1, nst);
            if (c + 1 >= 8) fill0(c + 1, nst);
            CP_COMMIT();
            asm volatile("cp.async.wait_group 1;" ::: "memory");
        } else {
            asm volatile("cp.async.wait_group 0;" ::: "memory");
        }
        __syncthreads();

        uint32_t sb = smb + (uint32_t)(st*STAGE_H)*2;
        #pragma unroll
        for (int k16 = 0; k16 < 2; k16++){
            int kb = k16*16;
            uint32_t ah[2][4], al[2][4];
            #pragma unroll
            for (int i = 0; i < 2; i++){
                uint32_t a = sb + (uint32_t)((wm*32 + i*16 + (lane & 15))*ESTR + kb + (lane >> 4)*8)*2;
                LDSM4(ah[i], a);
                LDSM4(al[i], a + TILE_H*2);
            }
            uint32_t bh[2][4], bl[2][4];
            {
                uint32_t bb = sb + (uint32_t)(2*TILE_H + (wn*64 + (lane & 15))*ESTR + kb + (lane >> 4)*8)*2;
                LDSM4(bh[0], bb);
                LDSM4(bl[0], bb + TILE_H*2);
            }
            #pragma unroll
            for (int jp = 0; jp < 4; jp++){
                int cur = jp & 1, nxt = cur ^ 1;
                if (jp < 3){
                    uint32_t bb = sb + (uint32_t)(2*TILE_H + (wn*64 + (jp+1)*16 + (lane & 15))*ESTR + kb + (lane >> 4)*8)*2;
                    LDSM4(bh[nxt], bb);
                    LDSM4(bl[nxt], bb + TILE_H*2);
                }
                MMA_F16(acc[0][jp*2+0], ah[0], bh[cur][0], bh[cur][2]);
                MMA_F16(acc[0][jp*2+1], ah[0], bh[cur][1], bh[cur][3]);
                MMA_F16(acc[1][jp*2+0], ah[1], bh[cur][0], bh[cur][2]);
                MMA_F16(acc[1][jp*2+1], ah[1], bh[cur][1], bh[cur][3]);
                MMA_F16(acc[0][jp*2+0], ah[0], bl[cur][0], bl[cur][2]);
                MMA_F16(acc[0][jp*2+1], ah[0], bl[cur][1], bl[cur][3]);
                MMA_F16(acc[1][jp*2+0], ah[1], bl[cur][0], bl[cur][2]);
                MMA_F16(acc[1][jp*2+1], ah[1], bl[cur][1], bl[cur][3]);
                MMA_F16(acc[0][jp*2+0], al[0], bh[cur][0], bh[cur][2]);
                MMA_F16(acc[0][jp*2+1], al[0], bh[cur][1], bh[cur][3]);
                MMA_F16(acc[1][jp*2+0], al[1], bh[cur][0], bh[cur][2]);
                MMA_F16(acc[1][jp*2+1], al[1], bh[cur][1], bh[cur][3]);
            }
        }
        __syncthreads();
    }

    float* aggr = g_aggr[layer];
    #pragma unroll
    for (int i = 0; i < 2; i++) {
        #pragma unroll
        for (int half = 0; half < 2; half++) {
            int row = wm*32 + i*16 + g + half*8;
            if (s_em[row] != 0.f) {
                const float* tD = g_tblD + (layer*10 + s_di[row])*Dd;
                const float* tR = g_tblR + ((size_t)layer*Rr + s_rel[row])*Dd;
                float* dst = aggr + (bN + s_tgt[row])*Dd;
                #pragma unroll
                for (int j = 0; j < 8; j++) {
                    int col = wn*64 + j*8 + t4*2;
                    float add0 = s_bias[col]   + __ldg(tD + col)     + __ldg(tR + col);
                    float add1 = s_bias[col+1] + __ldg(tD + col + 1) + __ldg(tR + col + 1);
                    float v0 = acc[i][j][half*2+0] + add0;
                    float v1 = acc[i][j][half*2+1] + add1;
                    if (v0 > 0.f) atomicAdd(dst + col,     v0);
                    if (v1 > 0.f) atomicAdd(dst + col + 1, v1);
                }
            }
        }
    }
}

// ---------------- node update GEMM (validated R16; .ca weights) ----------------
__global__ void __launch_bounds__(256, 3)
update_hmma_kernel(int layer, int write_split,
                   const float* __restrict__ bias,
                   const float* __restrict__ attW)
{
    extern __shared__ __half sm[];
    __shared__ float s_bias[128];

    int tid = threadIdx.x, wid = tid >> 5, lane = tid & 31;
    size_t r0 = (size_t)(blockIdx.x >> 1) * 128;
    int nb = blockIdx.x & 1;
    uint32_t smb = smem_u32(sm);

    {
        const __half* wh = g_updWhi + (size_t)layer*2*8192 + nb*64*64;
        const __half* wl = g_updWlo + (size_t)layer*2*8192 + nb*64*64;
        #pragma unroll
        for (int it = 0; it < 4; it++) {
            int idx = tid + it*256;
            int c = idx >> 9, r = idx & 511;
            int n = r >> 3, q = r & 7;
            uint32_t dhi = smb + (uint32_t)(UB_BASE + 2*c*UBT + n*USTR + q*8)*2;
            cpa16_ca(dhi,           wh + (size_t)c*8192 + n*64 + q*8);
            cpa16_ca(dhi + UBT*2,   wl + (size_t)c*8192 + n*64 + q*8);
        }
        CP_COMMIT();
    }
    if (tid < 128) s_bias[tid] = bias[tid];

    int wm = wid & 3, wn = wid >> 2;
    int g = lane >> 2, t4 = lane & 3;
    const float* aggr = g_aggr[layer];

    float acc[2][4][4];
    #pragma unroll
    for (int i = 0; i < 2; i++)
        #pragma unroll
        for (int j = 0; j < 4; j++)
            #pragma unroll
            for (int q = 0; q < 4; q++) acc[i][j][q] = 0.f;

    for (int c = 0; c < 2; c++) {
        int koff = c*64;
        #pragma unroll
        for (int it = 0; it < 8; it++) {
            int idx = tid + it*256;
            int row = idx >> 4, q = idx & 15;
            float4 v = *(const float4*)(aggr + (r0 + row)*Dd + koff + q*4);
            __half h0 = __float2half_rn(v.x), h1 = __float2half_rn(v.y);
            __half h2 = __float2half_rn(v.z), h3 = __float2half_rn(v.w);
            int ho = row*USTR + q*4;
            *(__half2*)(sm + ho)           = __halves2half2(h0, h1);
            *(__half2*)(sm + ho + 2)       = __halves2half2(h2, h3);
            *(__half2*)(sm + UAT + ho)     = __halves2half2(__float2half_rn(v.x-__half2float(h0)), __float2half_rn(v.y-__half2float(h1)));
            *(__half2*)(sm + UAT + ho + 2) = __halves2half2(__float2half_rn(v.z-__half2float(h2)), __float2half_rn(v.w-__half2float(h3)));
        }
        if (c == 0) asm volatile("cp.async.wait_group 0;" ::: "memory");
        __syncthreads();

        uint32_t bbase = smb + (uint32_t)(UB_BASE + 2*c*UBT)*2;
        #pragma unroll
        for (int k16 = 0; k16 < 4; k16++) {
            int kb = k16*16;
            uint32_t ahi[2][4], alo[2][4];
            #pragma unroll
            for (int i = 0; i < 2; i++) {
                uint32_t aadr = smb + (uint32_t)((wm*32 + i*16 + (lane & 15))*USTR + kb + (lane >> 4)*8)*2;
                LDSM4(ahi[i], aadr);
                LDSM4(alo[i], aadr + UAT*2);
            }
            #pragma unroll
            for (int jp = 0; jp < 2; jp++) {
                uint32_t bb = bbase + (uint32_t)((wn*32 + jp*16 + (lane & 15))*USTR + kb + (lane >> 4)*8)*2;
                uint32_t bh[4], bl[4];
                LDSM4(bh, bb);
                LDSM4(bl, bb + UBT*2);
                MMA_F16(acc[0][jp*2+0], ahi[0], bh[0], bh[2]);
                MMA_F16(acc[0][jp*2+1], ahi[0], bh[1], bh[3]);
                MMA_F16(acc[1][jp*2+0], ahi[1], bh[0], bh[2]);
                MMA_F16(acc[1][jp*2+1], ahi[1], bh[1], bh[3]);
                MMA_F16(acc[0][jp*2+0], ahi[0], bl[0], bl[2]);
                MMA_F16(acc[0][jp*2+1], ahi[0], bl[1], bl[3]);
                MMA_F16(acc[1][jp*2+0], ahi[1], bl[0], bl[2]);
                MMA_F16(acc[1][jp*2+1], ahi[1], bl[1], bl[3]);
                MMA_F16(acc[0][jp*2+0], alo[0], bh[0], bh[2]);
                MMA_F16(acc[0][jp*2+1], alo[0], bh[1], bh[3]);
                MMA_F16(acc[1][jp*2+0], alo[1], bh[0], bh[2]);
                MMA_F16(acc[1][jp*2+1], alo[1], bh[1], bh[3]);
            }
        }
        __syncthreads();
    }

    #pragma unroll
    for (int i = 0; i < 2; i++) {
        #pragma unroll
        for (int half = 0; half < 2; half++) {
            int row = wm*32 + i*16 + g + half*8;
            size_t gro = (r0 + row)*Dd;
            float* hp = g_h + gro;
            float part = 0.f;
            #pragma unroll
            for (int j = 0; j < 4; j++) {
                int col = nb*64 + wn*32 + j*8 + t4*2;
                float2 hv = *(float2*)(hp + col);
                float v0 = hv.x + acc[i][j][half*2+0] + s_bias[col];
                float v1 = hv.y + acc[i][j][half*2+1] + s_bias[col+1];
                *(float2*)(hp + col) = make_float2(v0, v1);
                if (write_split) {
                    uint32_t hi, lo;
                    pack2(make_float2(v0, v1), hi, lo);
                    *(uint32_t*)(g_hhi + gro + col) = hi;
                    *(uint32_t*)(g_hlo + gro + col) = lo;
                } else {
                    part = fmaf(v0, __ldg(attW + col), part);
                    part = fmaf(v1, __ldg(attW + col + 1), part);
                }
            }
            if (!write_split) atomicAdd(g_scores + r0 + row, part);
        }
    }
}

// ---------------- softmax + top-20 + output (validated R16) ----------------
__global__ void __launch_bounds__(1024)
topk_kernel(const int* __restrict__ node_mask, float* __restrict__ out,
            const float* __restrict__ attW, const float* __restrict__ attb,
            const float* __restrict__ rq)
{
    __shared__ float ss[Nn];
    __shared__ float rv[32];
    __shared__ int   ri[32];
    __shared__ float s_red;
    __shared__ int   top_i[Mm];
    __shared__ float top_v[Mm];

    int b = blockIdx.x;
    int t = threadIdx.x;
    int w = t >> 5, lane = t & 31;

    if (w == 0) {
        float s = 0.f;
        #pragma unroll
        for (int i = 0; i < 4; i++) {
            int d = lane + i*32;
            s = fmaf(rq[b*Dd + d], __ldg(attW + Dd + d), s);
        }
        #pragma unroll
        for (int o = 16; o; o >>= 1) s += __shfl_xor_sync(0xffffffffu, s, o);
        if (lane == 0) s_red = s + attb[0];
    }
    __syncthreads();
    float qadd = s_red;

    for (int i = t; i < Nn; i += 1024) {
        float s = g_scores[(size_t)b*Nn + i] + qadd;
        s = (s > 0.f) ? s : 0.01f * s;
        if (!node_mask[(size_t)b*Nn + i]) s = -1e9f;
        ss[i] = s;
    }
    __syncthreads();

    float m = -INFINITY;
    for (int i = t; i < Nn; i += 1024) m = fmaxf(m, ss[i]);
    #pragma unroll
    for (int o = 16; o; o >>= 1) m = fmaxf(m, __shfl_xor_sync(0xffffffffu, m, o));
    if (lane == 0) rv[w] = m;
    __syncthreads();
    if (w == 0) {
        float v = rv[lane];
        #pragma unroll
        for (int o = 16; o; o >>= 1) v = fmaxf(v, __shfl_xor_sync(0xffffffffu, v, o));
        if (lane == 0) s_red = v;
    }
    __syncthreads();
    float vmax = s_red;

    float sum = 0.f;
    for (int i = t; i < Nn; i += 1024) sum += expf(ss[i] - vmax);
    #pragma unroll
    for (int o = 16; o; o >>= 1) sum += __shfl_xor_sync(0xffffffffu, sum, o);
    if (lane == 0) rv[w] = sum;
    __syncthreads();
    if (w == 0) {
        float v = rv[lane];
        #pragma unroll
        for (int o = 16; o; o >>= 1) v += __shfl_xor_sync(0xffffffffu, v, o);
        if (lane == 0) s_red = v;
    }
    __syncthreads();
    float inv = 1.f / s_red;

    for (int sel = 0; sel < Mm; sel++) {
        float bv = -INFINITY; int bi = Nn;
        for (int i = t; i < Nn; i += 1024) {
            float v = ss[i];
            if (v > bv) { bv = v; bi = i; }
        }
        #pragma unroll
        for (int o = 16; o; o >>= 1) {
            float ov = __shfl_xor_sync(0xffffffffu, bv, o);
            int   oi = __shfl_xor_sync(0xffffffffu, bi, o);
            if (ov > bv || (ov == bv && oi < bi)) { bv = ov; bi = oi; }
        }
        if (lane == 0) { rv[w] = bv; ri[w] = bi; }
        __syncthreads();
        if (w == 0) {
            float v = rv[lane]; int vi = ri[lane];
            #pragma unroll
            for (int o = 16; o; o >>= 1) {
                float ov = __shfl_xor_sync(0xffffffffu, v, o);
                int   oi = __shfl_xor_sync(0xffffffffu, vi, o);
                if (ov > v || (ov == v && oi < vi)) { v = ov; vi = oi; }
            }
            if (lane == 0) { top_i[sel] = vi; top_v[sel] = v; ss[vi] = -INFINITY; }
        }
        __syncthreads();
    }

    for (int i = t; i < Mm*Dd; i += 1024) {
        int sel = i / Dd, d = i % Dd;
        int idx = top_i[sel];
        float alpha = expf(top_v[sel] - vmax) * inv;
        float mk = node_mask[(size_t)b*Nn + idx] ? 1.f : 0.f;
        float hv = g_h[((size_t)b*Nn + idx)*Dd + d] * mk;
        out[((size_t)b*Mm + sel)*Dd + d] = hv * alpha;
    }
    float m0 = node_mask[(size_t)b*Nn] ? 1.f : 0.f;
    for (int d = t; d < Dd; d += 1024)
        out[(size_t)Bk*Mm*Dd + (size_t)b*Dd + d] = g_h[((size_t)b*Nn)*Dd + d] * m0;
}

// ---------------- launch ----------------
extern "C" void kernel_launch(void* const* d_in, const int* in_sizes, int n_in,
                              void* d_out, int out_size)
{
    (void)in_sizes; (void)n_in; (void)out_size;
    const int*   dists      = (const int*)d_in[0];
    const int*   edge_index = (const int*)d_in[1];
    const int*   rels       = (const int*)d_in[2];
    const int*   node_mask  = (const int*)d_in[3];
    const int*   edge_mask  = (const int*)d_in[4];
    const float* rq         = (const float*)d_in[5];
    const float* conf       = (const float*)d_in[6];
    const float* noise      = (const float*)d_in[7];
    const float* dist_table = (const float*)d_in[8];
    const float* rel_table  = (const float*)d_in[9];
    const float* msg_W      = (const float*)d_in[10];
    const float* msg_b      = (const float*)d_in[11];
    const float* upd_W      = (const float*)d_in[12];
    const float* upd_b      = (const float*)d_in[13];
    const float* att_W      = (const float*)d_in[14];
    const float* att_b      = (const float*)d_in[15];
    float* out = (float*)d_out;

    cudaFuncSetAttribute(edge_hmma_kernel, cudaFuncAttributeMaxDynamicSharedMemorySize, ESMEM);
    cudaFuncSetAttribute(update_hmma_kernel, cudaFuncAttributeMaxDynamicSharedMemorySize, (int)USMEM);

    prep_all<<<(PREP_TOT + 255)/256, 256>>>(dists, noise, dist_table, conf,
                                            rel_table, msg_W, upd_W);

    for (int l = 0; l < Ll; l++) {
        edge_hmma_kernel<<<Bk*(Ee/128), 256, ESMEM>>>(
            l, edge_index, rels, edge_mask, dists, rel_table, msg_b + (size_t)l*Dd);
        update_hmma_kernel<<<2*Bk*Nn/128, 256, USMEM>>>(
            l, (l != Ll-1) ? 1 : 0, upd_b + (size_t)l*Dd, att_W);
    }

    topk_kernel<<<Bk, 1024>>>(node_mask, out, att_W, att_b, rq);
}